// round 8
// baseline (speedup 1.0000x reference)
#include <cuda_runtime.h>
#include <cuda_bf16.h>
#include <cfloat>
#include <cstdint>

#define N_EMBED  8192
#define E_DIM    64
#define N_QUERY  16384
#define MT       64                  // queries per CTA
#define NSLICE   2048                // codes per warp slice
#define NCHUNK   (NSLICE / 32)       // 64 chunks of 32 codes
#define CAND_MAX 160
#define MARGIN   0.5f

// ---------------- global scratch ----------------
__device__ __align__(16) float          g_norms[N_EMBED];
__device__ __align__(16) float          g_embT [N_EMBED * E_DIM];   // [code][k] fp32
__device__ __align__(16) __nv_bfloat16  g_ebf16[N_EMBED * E_DIM];   // [code][k] bf16
__device__ __align__(16) float          g_xq   [N_QUERY * E_DIM];   // [q][k] fp32
__device__ __align__(16) __nv_bfloat16  g_xbf16[N_QUERY * E_DIM];   // [q][k] bf16
__device__ int            g_cand [N_QUERY * CAND_MAX];
__device__ int            g_ncand[N_QUERY];

__device__ __forceinline__ void mma16816(float* c, const uint32_t* a,
                                         uint32_t b0, uint32_t b1) {
    asm volatile(
        "mma.sync.aligned.m16n8k16.row.col.f32.bf16.bf16.f32 "
        "{%0,%1,%2,%3}, {%4,%5,%6,%7}, {%8,%9}, {%0,%1,%2,%3};"
        : "+f"(c[0]), "+f"(c[1]), "+f"(c[2]), "+f"(c[3])
        : "r"(a[0]), "r"(a[1]), "r"(a[2]), "r"(a[3]), "r"(b0), "r"(b1));
}

// ---------------- fused prep kernel ----------------
__global__ void __launch_bounds__(256) prep_kernel(const float* __restrict__ x,
                                                   const float* __restrict__ embed) {
    const int bid = blockIdx.x;
    const int t = threadIdx.x;
    if (bid < 256) {                     // embed transpose (32 codes per block)
        __shared__ float s[64][33];
        int j0 = bid * 32;
#pragma unroll
        for (int it = 0; it < 8; ++it) {
            int idx = t + it * 256;
            int d = idx >> 5, jj = idx & 31;
            s[d][jj] = embed[d * N_EMBED + j0 + jj];
        }
        __syncthreads();
#pragma unroll
        for (int it = 0; it < 8; ++it) {
            int idx = t + it * 256;
            int jj = idx >> 6, d = idx & 63;
            float v = s[d][jj];
            g_embT [(j0 + jj) * E_DIM + d] = v;
            g_ebf16[(j0 + jj) * E_DIM + d] = __float2bfloat16(v);
        }
    } else if (bid < 768) {              // x transpose (32 queries) + counter reset
        __shared__ float s[64][33];
        int q0 = (bid - 256) * 32;
        int gt = (bid - 256) * 256 + t;
        if (gt < N_QUERY) g_ncand[gt] = 0;
        int b = q0 >> 10, hw0 = q0 & 1023;
#pragma unroll
        for (int it = 0; it < 8; ++it) {
            int idx = t + it * 256;
            int d = idx >> 5, qq = idx & 31;
            s[d][qq] = x[b * 65536 + d * 1024 + hw0 + qq];
        }
        __syncthreads();
#pragma unroll
        for (int it = 0; it < 8; ++it) {
            int idx = t + it * 256;
            int qq = idx >> 6, d = idx & 63;
            float v = s[d][qq];
            g_xq   [(q0 + qq) * E_DIM + d] = v;
            g_xbf16[(q0 + qq) * E_DIM + d] = __float2bfloat16(v);
        }
    } else {                             // code norms (256 codes per block)
        int j = (bid - 768) * 256 + t;
        float s = 0.f;
#pragma unroll
        for (int d = 0; d < E_DIM; ++d) {
            float v = embed[d * N_EMBED + j];
            s = fmaf(v, v, s);
        }
        g_norms[j] = s;
    }
}

// ---------------- main kernel: barrier-free, smem-free, LDG-fed HMMA ----------------
// 8 warps: wm = wid&1 (queries m0..m0+31), wn = wid>>1 (codes wn*2048..+2047)
__global__ void __launch_bounds__(256, 2) vq_mma_kernel() {
    const int tid  = threadIdx.x;
    const int lane = tid & 31;
    const int wid  = tid >> 5;
    const int m0   = (wid & 1) * 32;
    const int wn   = wid >> 1;
    const int q0   = blockIdx.x * MT;

    const int r0 = lane >> 2;            // fragment row within 8
    const int kc = (lane & 3) * 2;       // fragment k pair

    // ---- A fragments straight from global (row-major [q][k] bf16) ----
    uint32_t afrag[2][4][4];             // [mi][ks][4]
    {
        const char* ab = (const char*)(g_xbf16 + (size_t)(q0 + m0) * E_DIM);
#pragma unroll
        for (int mi = 0; mi < 2; ++mi)
#pragma unroll
            for (int ks = 0; ks < 4; ++ks) {
                const char* p = ab + (mi * 16 + r0) * 128 + ks * 32 + kc * 2;
                afrag[mi][ks][0] = *(const uint32_t*)(p);          // (m, k)
                afrag[mi][ks][1] = *(const uint32_t*)(p + 1024);   // (m+8, k)
                afrag[mi][ks][2] = *(const uint32_t*)(p + 16);     // (m, k+8)
                afrag[mi][ks][3] = *(const uint32_t*)(p + 1040);   // (m+8, k+8)
            }
    }

    float runbest[4] = {FLT_MAX, FLT_MAX, FLT_MAX, FLT_MAX};
    const int rbase = q0 + m0 + r0;      // +mi*16 +rr*8
    const char* bslice = (const char*)(g_ebf16 + (size_t)wn * NSLICE * E_DIM);

    for (int c = 0; c < NCHUNK; ++c) {
        const char* bp = bslice + (size_t)c * 32 * 128 + r0 * 128 + kc * 2;

        float acc[2][4][4];
#pragma unroll
        for (int mi = 0; mi < 2; ++mi)
#pragma unroll
            for (int nt = 0; nt < 4; ++nt)
#pragma unroll
                for (int e = 0; e < 4; ++e) acc[mi][nt][e] = 0.f;

#pragma unroll
        for (int ks = 0; ks < 4; ++ks) {
            uint32_t b0[4], b1[4];
#pragma unroll
            for (int nt = 0; nt < 4; ++nt) {
                const char* p = bp + nt * 1024 + ks * 32;   // code row = c*32+nt*8+r0
                b0[nt] = *(const uint32_t*)(p);
                b1[nt] = *(const uint32_t*)(p + 16);
            }
#pragma unroll
            for (int mi = 0; mi < 2; ++mi)
#pragma unroll
                for (int nt = 0; nt < 4; ++nt)
                    mma16816(acc[mi][nt], afrag[mi][ks], b0[nt], b1[nt]);
        }

        // ---- filter epilogue on register accumulators ----
        const int cb = wn * NSLICE + c * 32;
        float2 nv[4];
#pragma unroll
        for (int nt = 0; nt < 4; ++nt)
            nv[nt] = *(const float2*)(g_norms + cb + nt * 8 + kc);
#pragma unroll
        for (int mi = 0; mi < 2; ++mi)
#pragma unroll
            for (int rr = 0; rr < 2; ++rr) {
                const int q = rbase + mi * 16 + rr * 8;
                float rb = runbest[mi * 2 + rr];
#pragma unroll
                for (int nt = 0; nt < 4; ++nt)
#pragma unroll
                    for (int e = 0; e < 2; ++e) {
                        float nrm = e ? nv[nt].y : nv[nt].x;
                        float score = fmaf(-2.f, acc[mi][nt][rr * 2 + e], nrm);
                        if (score < rb + MARGIN) {
                            int pos = atomicAdd(&g_ncand[q], 1);
                            if (pos < CAND_MAX)
                                g_cand[q * CAND_MAX + pos] = cb + nt * 8 + kc + e;
                            rb = fminf(rb, score);
                        }
                    }
                runbest[mi * 2 + rr] = rb;
            }
        // tighten running minima across the 4 lanes sharing each query row
#pragma unroll
        for (int s = 0; s < 4; ++s) {
            runbest[s] = fminf(runbest[s], __shfl_xor_sync(0xFFFFFFFFu, runbest[s], 1));
            runbest[s] = fminf(runbest[s], __shfl_xor_sync(0xFFFFFFFFu, runbest[s], 2));
        }
    }
}

// ---------------- exact fp32 rescore + gather (candidate-per-lane) ----------------
__global__ void __launch_bounds__(256) rescore_kernel(float* __restrict__ out) {
    const int wid = threadIdx.x >> 5, lane = threadIdx.x & 31;
    const int q = blockIdx.x * 8 + wid;

    const float4* xr = (const float4*)(g_xq + (size_t)q * E_DIM);
    const int nc = g_ncand[q];

    float best = FLT_MAX;
    int bj = N_EMBED;

    if (nc <= CAND_MAX) {
        for (int base = 0; base < nc; base += 32) {
            int i = base + lane;
            float s = FLT_MAX;
            int j = N_EMBED;
            if (i < nc) {
                j = g_cand[q * CAND_MAX + i];
                const float4* er = (const float4*)(g_embT + (size_t)j * E_DIM);
                float p = 0.f;
#pragma unroll
                for (int t = 0; t < 16; ++t) {
                    float4 e = er[t], xx = xr[t];
                    p = fmaf(e.x, xx.x, p); p = fmaf(e.y, xx.y, p);
                    p = fmaf(e.z, xx.z, p); p = fmaf(e.w, xx.w, p);
                }
                s = fmaf(-2.f, p, g_norms[j]);
            }
            if (s < best || (s == best && j < bj)) { best = s; bj = j; }
        }
    } else {
        // overflow (rare): exact scan of all codes, candidate-per-lane
        for (int j0 = 0; j0 < N_EMBED; j0 += 32) {
            int j = j0 + lane;
            const float4* er = (const float4*)(g_embT + (size_t)j * E_DIM);
            float p = 0.f;
#pragma unroll
            for (int t = 0; t < 16; ++t) {
                float4 e = er[t], xx = xr[t];
                p = fmaf(e.x, xx.x, p); p = fmaf(e.y, xx.y, p);
                p = fmaf(e.z, xx.z, p); p = fmaf(e.w, xx.w, p);
            }
            float s = fmaf(-2.f, p, g_norms[j]);
            if (s < best || (s == best && j < bj)) { best = s; bj = j; }
        }
    }

    // lexicographic (score, index) warp argmin
#pragma unroll
    for (int off = 16; off > 0; off >>= 1) {
        float os = __shfl_xor_sync(0xFFFFFFFFu, best, off);
        int   oj = __shfl_xor_sync(0xFFFFFFFFu, bj, off);
        if (os < best || (os == best && oj < bj)) { best = os; bj = oj; }
    }

    out[(size_t)q * E_DIM + lane]      = g_embT[(size_t)bj * E_DIM + lane];
    out[(size_t)q * E_DIM + 32 + lane] = g_embT[(size_t)bj * E_DIM + 32 + lane];
}

// ---------------- launch ----------------
extern "C" void kernel_launch(void* const* d_in, const int* in_sizes, int n_in,
                              void* d_out, int out_size) {
    const float* x     = (const float*)d_in[0];   // [16,64,32,32]
    const float* embed = (const float*)d_in[1];   // [64,8192]
    float* out = (float*)d_out;                   // [16,32,32,64]

    prep_kernel<<<800, 256>>>(x, embed);
    vq_mma_kernel<<<N_QUERY / MT, 256>>>();
    rescore_kernel<<<N_QUERY / 8, 256>>>(out);
}

// round 9
// speedup vs baseline: 1.5598x; 1.5598x over previous
#include <cuda_runtime.h>
#include <cuda_bf16.h>
#include <cfloat>
#include <cstdint>

#define N_EMBED  8192
#define E_DIM    64
#define N_QUERY  16384
#define MT       64                  // queries per CTA
#define NSLICE   2048                // codes per warp slice
#define NCHUNK   (NSLICE / 32)       // 64 chunks of 32 codes
#define CAND_MAX 160
#define MARGIN   0.5f

// ---------------- global scratch ----------------
__device__ __align__(16) float g_norms[N_EMBED];
__device__ __align__(16) float g_embT [N_EMBED * E_DIM];   // [code][k] fp32 (rescore)
__device__ __align__(16) float g_xq   [N_QUERY * E_DIM];   // [q][k] fp32 (rescore)
// MMA-fragment-interleaved operands (built by prep):
//   bfrag[nb][ks][lane] = {b0,b1} for 8-code block nb, kstep ks
//   afrag[qb][ks][lane] = {a0,a1,a2,a3} for 16-query block qb
__device__ __align__(16) uint2 g_bfrag[N_EMBED / 8][4][32];
__device__ __align__(16) uint4 g_afrag[N_QUERY / 16][4][32];
__device__ int g_cand [N_QUERY * CAND_MAX];
__device__ int g_ncand[N_QUERY];

__device__ __forceinline__ void mma16816(float* c, const uint32_t* a,
                                         uint32_t b0, uint32_t b1) {
    asm volatile(
        "mma.sync.aligned.m16n8k16.row.col.f32.bf16.bf16.f32 "
        "{%0,%1,%2,%3}, {%4,%5,%6,%7}, {%8,%9}, {%0,%1,%2,%3};"
        : "+f"(c[0]), "+f"(c[1]), "+f"(c[2]), "+f"(c[3])
        : "r"(a[0]), "r"(a[1]), "r"(a[2]), "r"(a[3]), "r"(b0), "r"(b1));
}

__device__ __forceinline__ uint32_t pack_bf(float lo, float hi) {
    __nv_bfloat16 l = __float2bfloat16(lo), h = __float2bfloat16(hi);
    return (uint32_t)__bfloat16_as_ushort(l) | ((uint32_t)__bfloat16_as_ushort(h) << 16);
}

// ---------------- fused prep kernel ----------------
// blocks [0,256):   embed -> g_embT, g_norms, g_bfrag   (32 codes each)
// blocks [256,768): x     -> g_xq, g_afrag, ncand reset (32 queries each)
__global__ void __launch_bounds__(256) prep_kernel(const float* __restrict__ x,
                                                   const float* __restrict__ embed) {
    const int bid = blockIdx.x;
    const int t = threadIdx.x;
    __shared__ float s[64][33];

    if (bid < 256) {
        const int j0 = bid * 32;
#pragma unroll
        for (int it = 0; it < 8; ++it) {
            int idx = t + it * 256;
            int d = idx >> 5, jj = idx & 31;
            s[d][jj] = embed[d * N_EMBED + j0 + jj];
        }
        __syncthreads();
        // exact fp32 transpose for rescore
#pragma unroll
        for (int it = 0; it < 8; ++it) {
            int idx = t + it * 256;
            int jj = idx >> 6, d = idx & 63;
            g_embT[(j0 + jj) * E_DIM + d] = s[d][jj];
        }
        // code norms (32 threads)
        if (t < 32) {
            float sum = 0.f;
#pragma unroll
            for (int d = 0; d < E_DIM; ++d) { float v = s[d][t]; sum = fmaf(v, v, sum); }
            g_norms[j0 + t] = sum;
        }
        // B fragments: 4 nb-blocks x 4 ksteps x 32 lanes = 512 uint2, 2 per thread
#pragma unroll
        for (int h = 0; h < 2; ++h) {
            int item = t + h * 256;
            int lane = item & 31, grp = item >> 5;
            int lnb = grp & 3, ks = grp >> 2;
            int jl = lnb * 8 + (lane >> 2);
            int kb = ks * 16 + (lane & 3) * 2;
            uint2 v;
            v.x = pack_bf(s[kb][jl],     s[kb + 1][jl]);
            v.y = pack_bf(s[kb + 8][jl], s[kb + 9][jl]);
            g_bfrag[bid * 4 + lnb][ks][lane] = v;
        }
    } else {
        const int q0 = (bid - 256) * 32;
        const int gt = (bid - 256) * 256 + t;
        if (gt < N_QUERY) g_ncand[gt] = 0;       // fresh counters each graph replay
        const int b = q0 >> 10, hw0 = q0 & 1023;
#pragma unroll
        for (int it = 0; it < 8; ++it) {
            int idx = t + it * 256;
            int d = idx >> 5, qq = idx & 31;
            s[d][qq] = x[b * 65536 + d * 1024 + hw0 + qq];
        }
        __syncthreads();
#pragma unroll
        for (int it = 0; it < 8; ++it) {
            int idx = t + it * 256;
            int qq = idx >> 6, d = idx & 63;
            g_xq[(q0 + qq) * E_DIM + d] = s[d][qq];
        }
        // A fragments: 2 qb-blocks x 4 ksteps x 32 lanes = 256 uint4, 1 per thread
        {
            int lane = t & 31, grp = t >> 5;
            int lqb = grp & 1, ks = grp >> 1;
            int r = lqb * 16 + (lane >> 2);
            int kb = ks * 16 + (lane & 3) * 2;
            uint4 v;
            v.x = pack_bf(s[kb][r],         s[kb + 1][r]);
            v.y = pack_bf(s[kb][r + 8],     s[kb + 1][r + 8]);
            v.z = pack_bf(s[kb + 8][r],     s[kb + 9][r]);
            v.w = pack_bf(s[kb + 8][r + 8], s[kb + 9][r + 8]);
            g_afrag[(bid - 256) * 2 + lqb][ks][lane] = v;
        }
    }
}

// ---------------- chunk processor (32 codes) ----------------
template <bool PUSH>
__device__ __forceinline__ void do_chunk(int c, int wn, int lane, int rbase,
                                         const uint4 (&af)[2][4], float (&runbest)[4]) {
    const int nbb = wn * (NSLICE / 8) + c * 4;
    uint2 bf[4][4];
#pragma unroll
    for (int nt = 0; nt < 4; ++nt)
#pragma unroll
        for (int ks = 0; ks < 4; ++ks)
            bf[nt][ks] = g_bfrag[nbb + nt][ks][lane];   // LDG.64, 256B/warp contiguous

    float acc[2][4][4];
#pragma unroll
    for (int mi = 0; mi < 2; ++mi)
#pragma unroll
        for (int nt = 0; nt < 4; ++nt)
#pragma unroll
            for (int e = 0; e < 4; ++e) acc[mi][nt][e] = 0.f;

#pragma unroll
    for (int ks = 0; ks < 4; ++ks)
#pragma unroll
        for (int mi = 0; mi < 2; ++mi)
#pragma unroll
            for (int nt = 0; nt < 4; ++nt)
                mma16816(acc[mi][nt], (const uint32_t*)&af[mi][ks],
                         bf[nt][ks].x, bf[nt][ks].y);

    const int cb = wn * NSLICE + c * 32;
    const int kc = (lane & 3) * 2;
    float2 nv[4];
#pragma unroll
    for (int nt = 0; nt < 4; ++nt)
        nv[nt] = *(const float2*)(g_norms + cb + nt * 8 + kc);

#pragma unroll
    for (int mi = 0; mi < 2; ++mi)
#pragma unroll
        for (int rr = 0; rr < 2; ++rr) {
            const int q = rbase + mi * 16 + rr * 8;
            float rb = runbest[mi * 2 + rr];
#pragma unroll
            for (int nt = 0; nt < 4; ++nt)
#pragma unroll
                for (int e = 0; e < 2; ++e) {
                    float nrm = e ? nv[nt].y : nv[nt].x;
                    float score = fmaf(-2.f, acc[mi][nt][rr * 2 + e], nrm);
                    if (PUSH) {
                        if (score < rb + MARGIN) {
                            int pos = atomicAdd(&g_ncand[q], 1);
                            if (pos < CAND_MAX)
                                g_cand[q * CAND_MAX + pos] = cb + nt * 8 + kc + e;
                            rb = fminf(rb, score);
                        }
                    } else {
                        rb = fminf(rb, score);
                    }
                }
            runbest[mi * 2 + rr] = rb;
        }
    // share minima across the 4 lanes covering each query row
#pragma unroll
    for (int s2 = 0; s2 < 4; ++s2) {
        runbest[s2] = fminf(runbest[s2], __shfl_xor_sync(0xFFFFFFFFu, runbest[s2], 1));
        runbest[s2] = fminf(runbest[s2], __shfl_xor_sync(0xFFFFFFFFu, runbest[s2], 2));
    }
}

// ---------------- main kernel: barrier-free, smem-free, coalesced-fragment HMMA ----
// 8 warps: wid&1 -> 32-query m-group, wid>>1 -> 2048-code slice
__global__ void __launch_bounds__(256, 2) vq_mma_kernel() {
    const int tid  = threadIdx.x;
    const int lane = tid & 31;
    const int wid  = tid >> 5;
    const int m0   = (wid & 1) * 32;
    const int wn   = wid >> 1;
    const int q0   = blockIdx.x * MT;
    const int qb0  = (q0 + m0) / 16;

    uint4 af[2][4];
#pragma unroll
    for (int mi = 0; mi < 2; ++mi)
#pragma unroll
        for (int ks = 0; ks < 4; ++ks)
            af[mi][ks] = g_afrag[qb0 + mi][ks][lane];

    float runbest[4] = {FLT_MAX, FLT_MAX, FLT_MAX, FLT_MAX};
    const int rbase = q0 + m0 + (lane >> 2);

    // warmup: tighten runbest on chunk 0 without pushes (kills the cold-start
    // atomic burst; margin test only loosens, so candidate completeness holds)
    do_chunk<false>(0, wn, lane, rbase, af, runbest);

    for (int c = 0; c < NCHUNK; ++c)
        do_chunk<true>(c, wn, lane, rbase, af, runbest);
}

// ---------------- exact fp32 rescore + gather (candidate-per-lane) ----------------
__global__ void __launch_bounds__(256) rescore_kernel(float* __restrict__ out) {
    const int wid = threadIdx.x >> 5, lane = threadIdx.x & 31;
    const int q = blockIdx.x * 8 + wid;

    const float4* xr = (const float4*)(g_xq + (size_t)q * E_DIM);
    const int nc = g_ncand[q];

    float best = FLT_MAX;
    int bj = N_EMBED;

    if (nc <= CAND_MAX) {
        for (int base = 0; base < nc; base += 32) {
            int i = base + lane;
            float s = FLT_MAX;
            int j = N_EMBED;
            if (i < nc) {
                j = g_cand[q * CAND_MAX + i];
                const float4* er = (const float4*)(g_embT + (size_t)j * E_DIM);
                float p = 0.f;
#pragma unroll
                for (int t = 0; t < 16; ++t) {
                    float4 e = er[t], xx = xr[t];
                    p = fmaf(e.x, xx.x, p); p = fmaf(e.y, xx.y, p);
                    p = fmaf(e.z, xx.z, p); p = fmaf(e.w, xx.w, p);
                }
                s = fmaf(-2.f, p, g_norms[j]);
            }
            if (s < best || (s == best && j < bj)) { best = s; bj = j; }
        }
    } else {
        for (int j0 = 0; j0 < N_EMBED; j0 += 32) {     // overflow fallback (rare)
            int j = j0 + lane;
            const float4* er = (const float4*)(g_embT + (size_t)j * E_DIM);
            float p = 0.f;
#pragma unroll
            for (int t = 0; t < 16; ++t) {
                float4 e = er[t], xx = xr[t];
                p = fmaf(e.x, xx.x, p); p = fmaf(e.y, xx.y, p);
                p = fmaf(e.z, xx.z, p); p = fmaf(e.w, xx.w, p);
            }
            float s = fmaf(-2.f, p, g_norms[j]);
            if (s < best || (s == best && j < bj)) { best = s; bj = j; }
        }
    }

    // lexicographic (score, index) warp argmin
#pragma unroll
    for (int off = 16; off > 0; off >>= 1) {
        float os = __shfl_xor_sync(0xFFFFFFFFu, best, off);
        int   oj = __shfl_xor_sync(0xFFFFFFFFu, bj, off);
        if (os < best || (os == best && oj < bj)) { best = os; bj = oj; }
    }

    out[(size_t)q * E_DIM + lane]      = g_embT[(size_t)bj * E_DIM + lane];
    out[(size_t)q * E_DIM + 32 + lane] = g_embT[(size_t)bj * E_DIM + 32 + lane];
}

// ---------------- launch ----------------
extern "C" void kernel_launch(void* const* d_in, const int* in_sizes, int n_in,
                              void* d_out, int out_size) {
    const float* x     = (const float*)d_in[0];   // [16,64,32,32]
    const float* embed = (const float*)d_in[1];   // [64,8192]
    float* out = (float*)d_out;                   // [16,32,32,64]

    prep_kernel<<<768, 256>>>(x, embed);
    vq_mma_kernel<<<N_QUERY / MT, 256>>>();
    rescore_kernel<<<N_QUERY / 8, 256>>>(out);
}

// round 11
// speedup vs baseline: 1.7967x; 1.1519x over previous
#include <cuda_runtime.h>
#include <cuda_bf16.h>
#include <cfloat>
#include <cstdint>

#define N_EMBED  8192
#define E_DIM    64
#define N_QUERY  16384
#define MT       64                  // queries per CTA
#define NSLICE   2048                // codes per warp slice
#define NCHUNK   (NSLICE / 32)       // 64 chunks of 32 codes
#define CAND_MAX 160
#define MARGIN   0.5f

// ---------------- global scratch ----------------
__device__ __align__(16) float g_norms[N_EMBED];
__device__ __align__(16) float g_embT [N_EMBED * E_DIM];   // [code][k] fp32 (rescore)
__device__ __align__(16) float g_xq   [N_QUERY * E_DIM];   // [q][k] fp32 (rescore)
// MMA-fragment-interleaved operands (built by prep):
__device__ __align__(16) uint2 g_bfrag[N_EMBED / 8][4][32];
__device__ __align__(16) uint4 g_afrag[N_QUERY / 16][4][32];
__device__ int g_cand [N_QUERY * CAND_MAX];
__device__ int g_ncand[N_QUERY];

__device__ __forceinline__ void mma16816(float* c, const uint32_t* a,
                                         uint32_t b0, uint32_t b1) {
    asm volatile(
        "mma.sync.aligned.m16n8k16.row.col.f32.bf16.bf16.f32 "
        "{%0,%1,%2,%3}, {%4,%5,%6,%7}, {%8,%9}, {%0,%1,%2,%3};"
        : "+f"(c[0]), "+f"(c[1]), "+f"(c[2]), "+f"(c[3])
        : "r"(a[0]), "r"(a[1]), "r"(a[2]), "r"(a[3]), "r"(b0), "r"(b1));
}

__device__ __forceinline__ uint32_t pack_bf(float lo, float hi) {
    __nv_bfloat16 l = __float2bfloat16(lo), h = __float2bfloat16(hi);
    return (uint32_t)__bfloat16_as_ushort(l) | ((uint32_t)__bfloat16_as_ushort(h) << 16);
}

// ---------------- fused prep kernel ----------------
__global__ void __launch_bounds__(256) prep_kernel(const float* __restrict__ x,
                                                   const float* __restrict__ embed) {
    const int bid = blockIdx.x;
    const int t = threadIdx.x;
    __shared__ float s[64][33];

    if (bid < 256) {                                     // 32 codes per block
        const int j0 = bid * 32;
#pragma unroll
        for (int it = 0; it < 8; ++it) {
            int idx = t + it * 256;
            int d = idx >> 5, jj = idx & 31;
            s[d][jj] = embed[d * N_EMBED + j0 + jj];
        }
        __syncthreads();
#pragma unroll
        for (int it = 0; it < 8; ++it) {
            int idx = t + it * 256;
            int jj = idx >> 6, d = idx & 63;
            g_embT[(j0 + jj) * E_DIM + d] = s[d][jj];
        }
        if (t < 32) {
            float sum = 0.f;
#pragma unroll
            for (int d = 0; d < E_DIM; ++d) { float v = s[d][t]; sum = fmaf(v, v, sum); }
            g_norms[j0 + t] = sum;
        }
#pragma unroll
        for (int h = 0; h < 2; ++h) {
            int item = t + h * 256;
            int lane = item & 31, grp = item >> 5;
            int lnb = grp & 3, ks = grp >> 2;
            int jl = lnb * 8 + (lane >> 2);
            int kb = ks * 16 + (lane & 3) * 2;
            uint2 v;
            v.x = pack_bf(s[kb][jl],     s[kb + 1][jl]);
            v.y = pack_bf(s[kb + 8][jl], s[kb + 9][jl]);
            g_bfrag[bid * 4 + lnb][ks][lane] = v;
        }
    } else {                                             // 32 queries per block
        const int q0 = (bid - 256) * 32;
        const int gt = (bid - 256) * 256 + t;
        if (gt < N_QUERY) g_ncand[gt] = 0;
        const int b = q0 >> 10, hw0 = q0 & 1023;
#pragma unroll
        for (int it = 0; it < 8; ++it) {
            int idx = t + it * 256;
            int d = idx >> 5, qq = idx & 31;
            s[d][qq] = x[b * 65536 + d * 1024 + hw0 + qq];
        }
        __syncthreads();
#pragma unroll
        for (int it = 0; it < 8; ++it) {
            int idx = t + it * 256;
            int qq = idx >> 6, d = idx & 63;
            g_xq[(q0 + qq) * E_DIM + d] = s[d][qq];
        }
        {
            int lane = t & 31, grp = t >> 5;
            int lqb = grp & 1, ks = grp >> 1;
            int r = lqb * 16 + (lane >> 2);
            int kb = ks * 16 + (lane & 3) * 2;
            uint4 v;
            v.x = pack_bf(s[kb][r],         s[kb + 1][r]);
            v.y = pack_bf(s[kb][r + 8],     s[kb + 1][r + 8]);
            v.z = pack_bf(s[kb + 8][r],     s[kb + 9][r]);
            v.w = pack_bf(s[kb + 8][r + 8], s[kb + 9][r + 8]);
            g_afrag[(bid - 256) * 2 + lqb][ks][lane] = v;
        }
    }
}

// ---------------- main kernel: depth-3 pipelined, barrier-free HMMA ----------------
__global__ void __launch_bounds__(256, 2) vq_mma_kernel() {
    const int tid  = threadIdx.x;
    const int lane = tid & 31;
    const int wid  = tid >> 5;
    const int m0   = (wid & 1) * 32;
    const int wn   = wid >> 1;
    const int q0   = blockIdx.x * MT;
    const int qb0  = (q0 + m0) / 16;
    const int kc   = (lane & 3) * 2;
    const int rbase = q0 + m0 + (lane >> 2);

    uint4 af[2][4];
#pragma unroll
    for (int mi = 0; mi < 2; ++mi)
#pragma unroll
        for (int ks = 0; ks < 4; ++ks)
            af[mi][ks] = g_afrag[qb0 + mi][ks][lane];

    // per-warp base into fragment array: element (c,nt,ks) at bbase[c*512 + nt*128 + ks*32]
    const uint2* bbase = &g_bfrag[wn * (NSLICE / 8)][0][lane];

    float runbest[4] = {FLT_MAX, FLT_MAX, FLT_MAX, FLT_MAX};
    float2 nv[4];

    // ---- warmup: chunk 0, min-only (tightens runbest; no pushes) ----
    {
        uint2 wb[4][4];
#pragma unroll
        for (int nt = 0; nt < 4; ++nt)
#pragma unroll
            for (int ks = 0; ks < 4; ++ks)
                wb[nt][ks] = bbase[nt * 128 + ks * 32];
#pragma unroll
        for (int nt = 0; nt < 4; ++nt)
            nv[nt] = *(const float2*)(g_norms + wn * NSLICE + nt * 8 + kc);
        float acc[2][4][4];
#pragma unroll
        for (int mi = 0; mi < 2; ++mi)
#pragma unroll
            for (int nt = 0; nt < 4; ++nt)
#pragma unroll
                for (int e = 0; e < 4; ++e) acc[mi][nt][e] = 0.f;
#pragma unroll
        for (int ks = 0; ks < 4; ++ks)
#pragma unroll
            for (int mi = 0; mi < 2; ++mi)
#pragma unroll
                for (int nt = 0; nt < 4; ++nt)
                    mma16816(acc[mi][nt], (const uint32_t*)&af[mi][ks],
                             wb[nt][ks].x, wb[nt][ks].y);
#pragma unroll
        for (int mi = 0; mi < 2; ++mi)
#pragma unroll
            for (int rr = 0; rr < 2; ++rr) {
                float gm = FLT_MAX;
#pragma unroll
                for (int nt = 0; nt < 4; ++nt) {
                    gm = fminf(gm, fmaf(-2.f, acc[mi][nt][rr * 2],     nv[nt].x));
                    gm = fminf(gm, fmaf(-2.f, acc[mi][nt][rr * 2 + 1], nv[nt].y));
                }
                runbest[mi * 2 + rr] = gm;
            }
#pragma unroll
        for (int s2 = 0; s2 < 4; ++s2) {
            runbest[s2] = fminf(runbest[s2], __shfl_xor_sync(0xFFFFFFFFu, runbest[s2], 1));
            runbest[s2] = fminf(runbest[s2], __shfl_xor_sync(0xFFFFFFFFu, runbest[s2], 2));
        }
    }

    // ---- pipelined main loop ----
    uint2 ring[4][4];                    // [slot = ks][nt]
#pragma unroll
    for (int ks = 0; ks < 3; ++ks)       // prologue: steps 0..2 of chunk 0 (L1-hot)
#pragma unroll
        for (int nt = 0; nt < 4; ++nt)
            ring[ks][nt] = bbase[nt * 128 + ks * 32];

#pragma unroll 1
    for (int c = 0; c < NCHUNK; ++c) {
        const uint2* bc  = bbase + c * 512;
        const uint2* bcn = (c + 1 < NCHUNK) ? bc + 512 : bc;
        const int cb = wn * NSLICE + c * 32;

        float acc[2][4][4];
#pragma unroll
        for (int mi = 0; mi < 2; ++mi)
#pragma unroll
            for (int nt = 0; nt < 4; ++nt)
#pragma unroll
                for (int e = 0; e < 4; ++e) acc[mi][nt][e] = 0.f;

        // ks = 0: prefetch (c, ks3) -> slot3; load norms; mma slot0
#pragma unroll
        for (int nt = 0; nt < 4; ++nt) ring[3][nt] = bc[nt * 128 + 3 * 32];
#pragma unroll
        for (int nt = 0; nt < 4; ++nt)
            nv[nt] = *(const float2*)(g_norms + cb + nt * 8 + kc);
#pragma unroll
        for (int mi = 0; mi < 2; ++mi)
#pragma unroll
            for (int nt = 0; nt < 4; ++nt)
                mma16816(acc[mi][nt], (const uint32_t*)&af[mi][0],
                         ring[0][nt].x, ring[0][nt].y);

        // ks = 1: prefetch (c+1, ks0) -> slot0; mma slot1
#pragma unroll
        for (int nt = 0; nt < 4; ++nt) ring[0][nt] = bcn[nt * 128 + 0 * 32];
#pragma unroll
        for (int mi = 0; mi < 2; ++mi)
#pragma unroll
            for (int nt = 0; nt < 4; ++nt)
                mma16816(acc[mi][nt], (const uint32_t*)&af[mi][1],
                         ring[1][nt].x, ring[1][nt].y);

        // ks = 2: prefetch (c+1, ks1) -> slot1; mma slot2
#pragma unroll
        for (int nt = 0; nt < 4; ++nt) ring[1][nt] = bcn[nt * 128 + 1 * 32];
#pragma unroll
        for (int mi = 0; mi < 2; ++mi)
#pragma unroll
            for (int nt = 0; nt < 4; ++nt)
                mma16816(acc[mi][nt], (const uint32_t*)&af[mi][2],
                         ring[2][nt].x, ring[2][nt].y);

        // ks = 3: prefetch (c+1, ks2) -> slot2; mma slot3
#pragma unroll
        for (int nt = 0; nt < 4; ++nt) ring[2][nt] = bcn[nt * 128 + 2 * 32];
#pragma unroll
        for (int mi = 0; mi < 2; ++mi)
#pragma unroll
            for (int nt = 0; nt < 4; ++nt)
                mma16816(acc[mi][nt], (const uint32_t*)&af[mi][3],
                         ring[3][nt].x, ring[3][nt].y);

        // ---- group-min epilogue ----
#pragma unroll
        for (int mi = 0; mi < 2; ++mi)
#pragma unroll
            for (int rr = 0; rr < 2; ++rr) {
                const int i = mi * 2 + rr;
                float sc[8];
#pragma unroll
                for (int nt = 0; nt < 4; ++nt) {
                    sc[nt * 2]     = fmaf(-2.f, acc[mi][nt][rr * 2],     nv[nt].x);
                    sc[nt * 2 + 1] = fmaf(-2.f, acc[mi][nt][rr * 2 + 1], nv[nt].y);
                }
                float gm = fminf(fminf(fminf(sc[0], sc[1]), fminf(sc[2], sc[3])),
                                 fminf(fminf(sc[4], sc[5]), fminf(sc[6], sc[7])));
                const float th = runbest[i] + MARGIN;
                if (gm < th) {                         // rare
                    const int q = rbase + mi * 16 + rr * 8;
#pragma unroll
                    for (int nt = 0; nt < 4; ++nt)
#pragma unroll
                        for (int e = 0; e < 2; ++e)
                            if (sc[nt * 2 + e] < th) {
                                int pos = atomicAdd(&g_ncand[q], 1);
                                if (pos < CAND_MAX)
                                    g_cand[q * CAND_MAX + pos] = cb + nt * 8 + kc + e;
                            }
                }
                runbest[i] = fminf(runbest[i], gm);
            }
#pragma unroll
        for (int s2 = 0; s2 < 4; ++s2) {
            runbest[s2] = fminf(runbest[s2], __shfl_xor_sync(0xFFFFFFFFu, runbest[s2], 1));
            runbest[s2] = fminf(runbest[s2], __shfl_xor_sync(0xFFFFFFFFu, runbest[s2], 2));
        }
    }
}

// ---------------- exact fp32 rescore + gather (candidate-per-lane) ----------------
__global__ void __launch_bounds__(256) rescore_kernel(float* __restrict__ out) {
    const int wid = threadIdx.x >> 5, lane = threadIdx.x & 31;
    const int q = blockIdx.x * 8 + wid;

    const float4* xr = (const float4*)(g_xq + (size_t)q * E_DIM);
    const int nc = g_ncand[q];

    float best = FLT_MAX;
    int bj = N_EMBED;

    if (nc <= CAND_MAX) {
        for (int base = 0; base < nc; base += 32) {
            int i = base + lane;
            float s = FLT_MAX;
            int j = N_EMBED;
            if (i < nc) {
                j = g_cand[q * CAND_MAX + i];
                const float4* er = (const float4*)(g_embT + (size_t)j * E_DIM);
                float p = 0.f;
#pragma unroll
                for (int t = 0; t < 16; ++t) {
                    float4 e = er[t], xx = xr[t];
                    p = fmaf(e.x, xx.x, p); p = fmaf(e.y, xx.y, p);
                    p = fmaf(e.z, xx.z, p); p = fmaf(e.w, xx.w, p);
                }
                s = fmaf(-2.f, p, g_norms[j]);
            }
            if (s < best || (s == best && j < bj)) { best = s; bj = j; }
        }
    } else {
        for (int j0 = 0; j0 < N_EMBED; j0 += 32) {     // overflow fallback (rare)
            int j = j0 + lane;
            const float4* er = (const float4*)(g_embT + (size_t)j * E_DIM);
            float p = 0.f;
#pragma unroll
            for (int t = 0; t < 16; ++t) {
                float4 e = er[t], xx = xr[t];
                p = fmaf(e.x, xx.x, p); p = fmaf(e.y, xx.y, p);
                p = fmaf(e.z, xx.z, p); p = fmaf(e.w, xx.w, p);
            }
            float s = fmaf(-2.f, p, g_norms[j]);
            if (s < best || (s == best && j < bj)) { best = s; bj = j; }
        }
    }

#pragma unroll
    for (int off = 16; off > 0; off >>= 1) {
        float os = __shfl_xor_sync(0xFFFFFFFFu, best, off);
        int   oj = __shfl_xor_sync(0xFFFFFFFFu, bj, off);
        if (os < best || (os == best && oj < bj)) { best = os; bj = oj; }
    }

    out[(size_t)q * E_DIM + lane]      = g_embT[(size_t)bj * E_DIM + lane];
    out[(size_t)q * E_DIM + 32 + lane] = g_embT[(size_t)bj * E_DIM + 32 + lane];
}

// ---------------- launch ----------------
extern "C" void kernel_launch(void* const* d_in, const int* in_sizes, int n_in,
                              void* d_out, int out_size) {
    const float* x     = (const float*)d_in[0];   // [16,64,32,32]
    const float* embed = (const float*)d_in[1];   // [64,8192]
    float* out = (float*)d_out;                   // [16,32,32,64]

    prep_kernel<<<768, 256>>>(x, embed);
    vq_mma_kernel<<<N_QUERY / MT, 256>>>();
    rescore_kernel<<<N_QUERY / 8, 256>>>(out);
}

// round 13
// speedup vs baseline: 2.2524x; 1.2536x over previous
#include <cuda_runtime.h>
#include <cuda_bf16.h>
#include <cfloat>
#include <cstdint>

#define N_EMBED  8192
#define E_DIM    64
#define N_QUERY  16384
#define MT       128                 // queries per CTA
#define NHALF    (N_EMBED / 2)       // codes per warp-group half
#define NCHUNK_H (NHALF / 32)        // 128 chunks of 32 codes
#define CAND_MAX 160
#define MARGIN   0.5f

// ---------------- global scratch ----------------
__device__ __align__(16) float g_norms[N_EMBED];
__device__ __align__(16) float g_embT [N_EMBED * E_DIM];   // [code][k] fp32 (rescore)
__device__ __align__(16) float g_xq   [N_QUERY * E_DIM];   // [q][k] fp32 (rescore)
// MMA-fragment-interleaved operands (built by prep):
__device__ __align__(16) uint2 g_bfrag[N_EMBED / 8][4][32];
__device__ __align__(16) uint4 g_afrag[N_QUERY / 16][4][32];
__device__ int g_cand [N_QUERY * CAND_MAX];
__device__ int g_ncand[N_QUERY];

__device__ __forceinline__ void mma16816(float* c, const uint32_t* a,
                                         uint32_t b0, uint32_t b1) {
    asm volatile(
        "mma.sync.aligned.m16n8k16.row.col.f32.bf16.bf16.f32 "
        "{%0,%1,%2,%3}, {%4,%5,%6,%7}, {%8,%9}, {%0,%1,%2,%3};"
        : "+f"(c[0]), "+f"(c[1]), "+f"(c[2]), "+f"(c[3])
        : "r"(a[0]), "r"(a[1]), "r"(a[2]), "r"(a[3]), "r"(b0), "r"(b1));
}

__device__ __forceinline__ uint32_t pack_bf(float lo, float hi) {
    __nv_bfloat16 l = __float2bfloat16(lo), h = __float2bfloat16(hi);
    return (uint32_t)__bfloat16_as_ushort(l) | ((uint32_t)__bfloat16_as_ushort(h) << 16);
}

// ---------------- fused prep kernel ----------------
__global__ void __launch_bounds__(256) prep_kernel(const float* __restrict__ x,
                                                   const float* __restrict__ embed) {
    const int bid = blockIdx.x;
    const int t = threadIdx.x;
    __shared__ float s[64][33];

    if (bid < 256) {                                     // 32 codes per block
        const int j0 = bid * 32;
#pragma unroll
        for (int it = 0; it < 8; ++it) {
            int idx = t + it * 256;
            int d = idx >> 5, jj = idx & 31;
            s[d][jj] = embed[d * N_EMBED + j0 + jj];
        }
        __syncthreads();
#pragma unroll
        for (int it = 0; it < 8; ++it) {
            int idx = t + it * 256;
            int jj = idx >> 6, d = idx & 63;
            g_embT[(j0 + jj) * E_DIM + d] = s[d][jj];
        }
        if (t < 32) {
            float sum = 0.f;
#pragma unroll
            for (int d = 0; d < E_DIM; ++d) { float v = s[d][t]; sum = fmaf(v, v, sum); }
            g_norms[j0 + t] = sum;
        }
#pragma unroll
        for (int h = 0; h < 2; ++h) {
            int item = t + h * 256;
            int lane = item & 31, grp = item >> 5;
            int lnb = grp & 3, ks = grp >> 2;
            int jl = lnb * 8 + (lane >> 2);
            int kb = ks * 16 + (lane & 3) * 2;
            uint2 v;
            v.x = pack_bf(s[kb][jl],     s[kb + 1][jl]);
            v.y = pack_bf(s[kb + 8][jl], s[kb + 9][jl]);
            g_bfrag[bid * 4 + lnb][ks][lane] = v;
        }
    } else {                                             // 32 queries per block
        const int q0 = (bid - 256) * 32;
        const int gt = (bid - 256) * 256 + t;
        if (gt < N_QUERY) g_ncand[gt] = 0;
        const int b = q0 >> 10, hw0 = q0 & 1023;
#pragma unroll
        for (int it = 0; it < 8; ++it) {
            int idx = t + it * 256;
            int d = idx >> 5, qq = idx & 31;
            s[d][qq] = x[b * 65536 + d * 1024 + hw0 + qq];
        }
        __syncthreads();
#pragma unroll
        for (int it = 0; it < 8; ++it) {
            int idx = t + it * 256;
            int qq = idx >> 6, d = idx & 63;
            g_xq[(q0 + qq) * E_DIM + d] = s[d][qq];
        }
        {
            int lane = t & 31, grp = t >> 5;
            int lqb = grp & 1, ks = grp >> 1;
            int r = lqb * 16 + (lane >> 2);
            int kb = ks * 16 + (lane & 3) * 2;
            uint4 v;
            v.x = pack_bf(s[kb][r],         s[kb + 1][r]);
            v.y = pack_bf(s[kb][r + 8],     s[kb + 1][r + 8]);
            v.z = pack_bf(s[kb + 8][r],     s[kb + 9][r]);
            v.w = pack_bf(s[kb + 8][r + 8], s[kb + 9][r + 8]);
            g_afrag[(bid - 256) * 2 + lqb][ks][lane] = v;
        }
    }
}

// ---------------- main kernel: L1-cooperative, pipelined, barrier-free HMMA -------
// 16 warps: wg = wid>>3 (code half, 4096 codes), wl = wid&7 (16-query m-block).
// All 8 warps of a half walk the SAME chunk stream -> L1 serves 7/8 of B reads.
__global__ void __launch_bounds__(512, 1) vq_mma_kernel() {
    const int tid  = threadIdx.x;
    const int lane = tid & 31;
    const int wid  = tid >> 5;
    const int wg   = wid >> 3;           // code half
    const int wl   = wid & 7;            // m-block within CTA
    const int q0   = blockIdx.x * MT + wl * 16;
    const int qb   = blockIdx.x * 8 + wl;
    const int kc   = (lane & 3) * 2;
    const int rbase = q0 + (lane >> 2);

    uint4 af[4];
#pragma unroll
    for (int ks = 0; ks < 4; ++ks) af[ks] = g_afrag[qb][ks][lane];

    // chunk c element (nt,ks) at bbase[c*512 + nt*128 + ks*32]
    const uint2* bbase = &g_bfrag[wg * (NHALF / 8)][0][lane];
    const int nbase = wg * NHALF;

    float runbest[2] = {FLT_MAX, FLT_MAX};
    float2 nv[4];

    // ---- warmup: chunk 0, min-only (tightens runbest; no pushes) ----
    {
        uint2 wb[4][4];
#pragma unroll
        for (int nt = 0; nt < 4; ++nt)
#pragma unroll
            for (int ks = 0; ks < 4; ++ks)
                wb[nt][ks] = bbase[nt * 128 + ks * 32];
#pragma unroll
        for (int nt = 0; nt < 4; ++nt)
            nv[nt] = *(const float2*)(g_norms + nbase + nt * 8 + kc);
        float acc[4][4];
#pragma unroll
        for (int nt = 0; nt < 4; ++nt)
#pragma unroll
            for (int e = 0; e < 4; ++e) acc[nt][e] = 0.f;
#pragma unroll
        for (int ks = 0; ks < 4; ++ks)
#pragma unroll
            for (int nt = 0; nt < 4; ++nt)
                mma16816(acc[nt], (const uint32_t*)&af[ks], wb[nt][ks].x, wb[nt][ks].y);
#pragma unroll
        for (int rr = 0; rr < 2; ++rr) {
            float gm = FLT_MAX;
#pragma unroll
            for (int nt = 0; nt < 4; ++nt) {
                gm = fminf(gm, fmaf(-2.f, acc[nt][rr * 2],     nv[nt].x));
                gm = fminf(gm, fmaf(-2.f, acc[nt][rr * 2 + 1], nv[nt].y));
            }
            runbest[rr] = gm;
        }
#pragma unroll
        for (int s2 = 0; s2 < 2; ++s2) {
            runbest[s2] = fminf(runbest[s2], __shfl_xor_sync(0xFFFFFFFFu, runbest[s2], 1));
            runbest[s2] = fminf(runbest[s2], __shfl_xor_sync(0xFFFFFFFFu, runbest[s2], 2));
        }
    }

    // ---- pipelined main loop over this half's 128 chunks ----
    uint2 ring[4][4];                    // [slot = ks][nt]
#pragma unroll
    for (int ks = 0; ks < 3; ++ks)       // prologue (L1-hot from warmup)
#pragma unroll
        for (int nt = 0; nt < 4; ++nt)
            ring[ks][nt] = bbase[nt * 128 + ks * 32];

#pragma unroll 1
    for (int c = 0; c < NCHUNK_H; ++c) {
        const uint2* bc  = bbase + c * 512;
        const uint2* bcn = (c + 1 < NCHUNK_H) ? bc + 512 : bc;
        const int cb = nbase + c * 32;

        float acc[4][4];
#pragma unroll
        for (int nt = 0; nt < 4; ++nt)
#pragma unroll
            for (int e = 0; e < 4; ++e) acc[nt][e] = 0.f;

        // ks = 0: prefetch (c, ks3) -> slot3; load norms; mma slot0
#pragma unroll
        for (int nt = 0; nt < 4; ++nt) ring[3][nt] = bc[nt * 128 + 3 * 32];
#pragma unroll
        for (int nt = 0; nt < 4; ++nt)
            nv[nt] = *(const float2*)(g_norms + cb + nt * 8 + kc);
#pragma unroll
        for (int nt = 0; nt < 4; ++nt)
            mma16816(acc[nt], (const uint32_t*)&af[0], ring[0][nt].x, ring[0][nt].y);

        // ks = 1: prefetch (c+1, ks0) -> slot0; mma slot1
#pragma unroll
        for (int nt = 0; nt < 4; ++nt) ring[0][nt] = bcn[nt * 128 + 0 * 32];
#pragma unroll
        for (int nt = 0; nt < 4; ++nt)
            mma16816(acc[nt], (const uint32_t*)&af[1], ring[1][nt].x, ring[1][nt].y);

        // ks = 2: prefetch (c+1, ks1) -> slot1; mma slot2
#pragma unroll
        for (int nt = 0; nt < 4; ++nt) ring[1][nt] = bcn[nt * 128 + 1 * 32];
#pragma unroll
        for (int nt = 0; nt < 4; ++nt)
            mma16816(acc[nt], (const uint32_t*)&af[2], ring[2][nt].x, ring[2][nt].y);

        // ks = 3: prefetch (c+1, ks2) -> slot2; mma slot3
#pragma unroll
        for (int nt = 0; nt < 4; ++nt) ring[2][nt] = bcn[nt * 128 + 2 * 32];
#pragma unroll
        for (int nt = 0; nt < 4; ++nt)
            mma16816(acc[nt], (const uint32_t*)&af[3], ring[3][nt].x, ring[3][nt].y);

        // ---- group-min epilogue ----
#pragma unroll
        for (int rr = 0; rr < 2; ++rr) {
            float sc[8];
#pragma unroll
            for (int nt = 0; nt < 4; ++nt) {
                sc[nt * 2]     = fmaf(-2.f, acc[nt][rr * 2],     nv[nt].x);
                sc[nt * 2 + 1] = fmaf(-2.f, acc[nt][rr * 2 + 1], nv[nt].y);
            }
            float gm = fminf(fminf(fminf(sc[0], sc[1]), fminf(sc[2], sc[3])),
                             fminf(fminf(sc[4], sc[5]), fminf(sc[6], sc[7])));
            const float th = runbest[rr] + MARGIN;
            if (gm < th) {                          // rare
                const int q = rbase + rr * 8;
#pragma unroll
                for (int nt = 0; nt < 4; ++nt)
#pragma unroll
                    for (int e = 0; e < 2; ++e)
                        if (sc[nt * 2 + e] < th) {
                            int pos = atomicAdd(&g_ncand[q], 1);
                            if (pos < CAND_MAX)
                                g_cand[q * CAND_MAX + pos] = cb + nt * 8 + kc + e;
                        }
            }
            runbest[rr] = fminf(runbest[rr], gm);
        }
#pragma unroll
        for (int s2 = 0; s2 < 2; ++s2) {
            runbest[s2] = fminf(runbest[s2], __shfl_xor_sync(0xFFFFFFFFu, runbest[s2], 1));
            runbest[s2] = fminf(runbest[s2], __shfl_xor_sync(0xFFFFFFFFu, runbest[s2], 2));
        }
    }
}

// ---------------- exact fp32 rescore + gather (candidate-per-lane) ----------------
__global__ void __launch_bounds__(256) rescore_kernel(float* __restrict__ out) {
    const int wid = threadIdx.x >> 5, lane = threadIdx.x & 31;
    const int q = blockIdx.x * 8 + wid;

    const float4* xr = (const float4*)(g_xq + (size_t)q * E_DIM);
    const int nc = g_ncand[q];

    float best = FLT_MAX;
    int bj = N_EMBED;

    if (nc <= CAND_MAX) {
        for (int base = 0; base < nc; base += 32) {
            int i = base + lane;
            float s = FLT_MAX;
            int j = N_EMBED;
            if (i < nc) {
                j = g_cand[q * CAND_MAX + i];
                const float4* er = (const float4*)(g_embT + (size_t)j * E_DIM);
                float p = 0.f;
#pragma unroll
                for (int t = 0; t < 16; ++t) {
                    float4 e = er[t], xx = xr[t];
                    p = fmaf(e.x, xx.x, p); p = fmaf(e.y, xx.y, p);
                    p = fmaf(e.z, xx.z, p); p = fmaf(e.w, xx.w, p);
                }
                s = fmaf(-2.f, p, g_norms[j]);
            }
            if (s < best || (s == best && j < bj)) { best = s; bj = j; }
        }
    } else {
        for (int j0 = 0; j0 < N_EMBED; j0 += 32) {     // overflow fallback (rare)
            int j = j0 + lane;
            const float4* er = (const float4*)(g_embT + (size_t)j * E_DIM);
            float p = 0.f;
#pragma unroll
            for (int t = 0; t < 16; ++t) {
                float4 e = er[t], xx = xr[t];
                p = fmaf(e.x, xx.x, p); p = fmaf(e.y, xx.y, p);
                p = fmaf(e.z, xx.z, p); p = fmaf(e.w, xx.w, p);
            }
            float s = fmaf(-2.f, p, g_norms[j]);
            if (s < best || (s == best && j < bj)) { best = s; bj = j; }
        }
    }

#pragma unroll
    for (int off = 16; off > 0; off >>= 1) {
        float os = __shfl_xor_sync(0xFFFFFFFFu, best, off);
        int   oj = __shfl_xor_sync(0xFFFFFFFFu, bj, off);
        if (os < best || (os == best && oj < bj)) { best = os; bj = oj; }
    }

    out[(size_t)q * E_DIM + lane]      = g_embT[(size_t)bj * E_DIM + lane];
    out[(size_t)q * E_DIM + 32 + lane] = g_embT[(size_t)bj * E_DIM + 32 + lane];
}

// ---------------- launch ----------------
extern "C" void kernel_launch(void* const* d_in, const int* in_sizes, int n_in,
                              void* d_out, int out_size) {
    const float* x     = (const float*)d_in[0];   // [16,64,32,32]
    const float* embed = (const float*)d_in[1];   // [64,8192]
    float* out = (float*)d_out;                   // [16,32,32,64]

    prep_kernel<<<768, 256>>>(x, embed);
    vq_mma_kernel<<<N_QUERY / MT, 512>>>();
    rescore_kernel<<<N_QUERY / 8, 256>>>(out);
}